// round 1
// baseline (speedup 1.0000x reference)
#include <cuda_runtime.h>
#include <cuda_bf16.h>
#include <cstdint>

// Problem constants
#define BATCH   32
#define DDIM    512
#define HW      1024           // 32*32
#define NROWS   32768          // BATCH*HW
#define KCODES  4096
#define IMG_ELEMS 16777216     // 32*512*32*32

// GEMM tiling
#define BM 128
#define BN 128
#define BK 16
#define TM 8
#define TN 8

// ---------------- device scratch (no allocations allowed) ----------------
__device__ float g_znorm[NROWS];
__device__ float g_enorm[KCODES];
__device__ float g_smin[NROWS];   // min over codes of (||e||^2 - 2 z.e)
__device__ int   g_kmin[NROWS];

// ---------------- kernel 1: per-row ||z||^2 ----------------
// row = b*1024 + hw ; inputs[b, d, hw] = inp[b*524288 + d*1024 + hw]
// consecutive threads -> consecutive hw -> fully coalesced per d.
__global__ void znorm_kernel(const float* __restrict__ inp) {
    int row = blockIdx.x * 256 + threadIdx.x;
    int b = row >> 10, hw = row & 1023;
    const float* p = inp + (size_t)b * 524288 + hw;
    float s = 0.0f;
    #pragma unroll 8
    for (int d = 0; d < DDIM; d++) {
        float v = p[(size_t)d * 1024];
        s = fmaf(v, v, s);
    }
    g_znorm[row] = s;
}

// ---------------- kernel 2: per-code ||e||^2 ----------------
__global__ void enorm_kernel(const float* __restrict__ emb) {
    int code = blockIdx.x;
    const float4* p = reinterpret_cast<const float4*>(emb + (size_t)code * DDIM);
    int t = threadIdx.x;  // 128 threads, 128 float4 = 512 floats
    float4 v = p[t];
    float s = v.x*v.x + v.y*v.y + v.z*v.z + v.w*v.w;
    #pragma unroll
    for (int off = 16; off; off >>= 1) s += __shfl_down_sync(0xffffffffu, s, off);
    __shared__ float ws[4];
    if ((t & 31) == 0) ws[t >> 5] = s;
    __syncthreads();
    if (t == 0) g_enorm[code] = ws[0] + ws[1] + ws[2] + ws[3];
}

// ---------------- kernel 3: fused SGEMM + argmin ----------------
// Each CTA: 128 consecutive rows (same batch b since 128 | 1024) x all 4096 codes.
// acc = z . e ; score s = ||e||^2 - 2*acc ; track running (min, argmin) per row.
__global__ void __launch_bounds__(256, 2)
gemm_argmin_kernel(const float* __restrict__ inp, const float* __restrict__ emb) {
    __shared__ float As[BK][BM];
    __shared__ float Bs[BK][BN];

    const int tid = threadIdx.x;
    const int tx = tid & 15;        // 0..15  -> 8 codes each
    const int ty = tid >> 4;        // 0..15  -> 8 rows each
    const int row0 = blockIdx.x * BM;
    const int b    = row0 >> 10;
    const int hw0  = row0 & 1023;
    const float* Abase = inp + (size_t)b * 524288 + hw0;

    float best[TM];
    int   bidx[TM];
    #pragma unroll
    for (int i = 0; i < TM; i++) { best[i] = 3.4e38f; bidx[i] = 0; }

    for (int nc0 = 0; nc0 < KCODES; nc0 += BN) {
        float acc[TM][TN];
        #pragma unroll
        for (int i = 0; i < TM; i++)
            #pragma unroll
            for (int j = 0; j < TN; j++) acc[i][j] = 0.0f;

        for (int d0 = 0; d0 < DDIM; d0 += BK) {
            // Load A tile [BK x BM]: linear over 2048 elems, 8 per thread.
            // For fixed k, 128 consecutive rows are contiguous floats -> coalesced.
            #pragma unroll
            for (int i = 0; i < 8; i++) {
                int l = tid + i * 256;
                int k = l >> 7;
                int r = l & 127;
                As[k][r] = Abase[(size_t)(d0 + k) * 1024 + r];
            }
            // Load B tile [BK x BN]: each thread loads 2 float4 of one code row.
            {
                int c  = tid >> 1;
                int k0 = (tid & 1) * 8;
                const float4* src = reinterpret_cast<const float4*>(
                    emb + (size_t)(nc0 + c) * DDIM + d0 + k0);
                float4 v0 = src[0];
                float4 v1 = src[1];
                Bs[k0 + 0][c] = v0.x; Bs[k0 + 1][c] = v0.y;
                Bs[k0 + 2][c] = v0.z; Bs[k0 + 3][c] = v0.w;
                Bs[k0 + 4][c] = v1.x; Bs[k0 + 5][c] = v1.y;
                Bs[k0 + 6][c] = v1.z; Bs[k0 + 7][c] = v1.w;
            }
            __syncthreads();

            #pragma unroll
            for (int k = 0; k < BK; k++) {
                float a[TM], bb[TN];
                #pragma unroll
                for (int i = 0; i < TM; i++) a[i] = As[k][ty * TM + i];
                #pragma unroll
                for (int j = 0; j < TN; j++) bb[j] = Bs[k][tx * TN + j];
                #pragma unroll
                for (int i = 0; i < TM; i++)
                    #pragma unroll
                    for (int j = 0; j < TN; j++)
                        acc[i][j] = fmaf(a[i], bb[j], acc[i][j]);
            }
            __syncthreads();
        }

        // Epilogue: s = ||e||^2 - 2*acc, running min (ascending code order ->
        // strict < preserves first-occurrence semantics per thread).
        #pragma unroll
        for (int j = 0; j < TN; j++) {
            int code = nc0 + tx * TN + j;
            float en = __ldg(&g_enorm[code]);
            #pragma unroll
            for (int i = 0; i < TM; i++) {
                float s = fmaf(-2.0f, acc[i][j], en);
                if (s < best[i]) { best[i] = s; bidx[i] = code; }
            }
        }
    }

    // Reduce across the 16 tx-threads sharing each row (16-lane shfl groups;
    // ties resolved to the smaller code index, matching jnp.argmin).
    unsigned lane = tid & 31;
    #pragma unroll
    for (int i = 0; i < TM; i++) {
        float v = best[i];
        int   ix = bidx[i];
        #pragma unroll
        for (int off = 8; off >= 1; off >>= 1) {
            float ov = __shfl_down_sync(0xffffffffu, v, off);
            int   oi = __shfl_down_sync(0xffffffffu, ix, off);
            if (ov < v || (ov == v && oi < ix)) { v = ov; ix = oi; }
        }
        if ((lane & 15) == 0) {
            int grow = row0 + ty * TM + i;
            g_smin[grow] = v;
            g_kmin[grow] = ix;
        }
    }
}

// ---------------- kernel 4: deterministic loss reduce ----------------
// loss = 1.25 * sum_rows(znorm + smin) / (N*D)
__global__ void loss_kernel(float* __restrict__ out, int out_size) {
    __shared__ float sm[256];
    float s = 0.0f;
    for (int i = threadIdx.x; i < NROWS; i += 256)
        s += g_znorm[i] + g_smin[i];
    sm[threadIdx.x] = s;
    __syncthreads();
    #pragma unroll
    for (int off = 128; off; off >>= 1) {
        if (threadIdx.x < off) sm[threadIdx.x] += sm[threadIdx.x + off];
        __syncthreads();
    }
    if (threadIdx.x == 0 && out_size > IMG_ELEMS)
        out[IMG_ELEMS] = 1.25f * sm[0] / ((float)NROWS * (float)DDIM);
}

// ---------------- kernel 5: gather + NHWC->NCHW writeback ----------------
// Tile: 32 rows x 32 channels, SMEM transpose so both the embedding reads
// (contiguous along c) and the output writes (contiguous along hw) coalesce.
__global__ void gather_kernel(const float* __restrict__ emb, float* __restrict__ out) {
    __shared__ float sm[32][33];
    __shared__ int ks[32];
    int row0 = blockIdx.x * 32;     // 1024 row tiles
    int c0   = blockIdx.y * 32;     // 16 channel tiles
    int t = threadIdx.x;            // 256 threads
    if (t < 32) ks[t] = g_kmin[row0 + t];
    __syncthreads();

    int rl = t >> 5;   // 0..7
    int cl = t & 31;
    #pragma unroll
    for (int i = 0; i < 4; i++) {
        int r = rl + i * 8;
        sm[r][cl] = emb[(size_t)ks[r] * DDIM + c0 + cl];
    }
    __syncthreads();

    int b   = row0 >> 10;
    int hw0 = row0 & 1023;
    #pragma unroll
    for (int i = 0; i < 4; i++) {
        int cw = (t >> 5) + i * 8;
        int rw = t & 31;
        out[(size_t)b * 524288 + (size_t)(c0 + cw) * 1024 + hw0 + rw] = sm[rw][cw];
    }
}

// ---------------- launch ----------------
extern "C" void kernel_launch(void* const* d_in, const int* in_sizes, int n_in,
                              void* d_out, int out_size) {
    const float* inp = (const float*)d_in[0];   // [32,512,32,32]
    const float* emb = (const float*)d_in[1];   // [4096,512]
    float* out = (float*)d_out;

    znorm_kernel<<<NROWS / 256, 256>>>(inp);
    enorm_kernel<<<KCODES, 128>>>(emb);
    gemm_argmin_kernel<<<NROWS / BM, 256>>>(inp, emb);
    loss_kernel<<<1, 256>>>(out, out_size);
    gather_kernel<<<dim3(NROWS / 32, DDIM / 32), 256>>>(emb, out);
}